// round 15
// baseline (speedup 1.0000x reference)
#include <cuda_runtime.h>
#include <cuda_fp16.h>
#include <cstdint>

// ============================================================================
// LSTMCell on GB300 via mma.sync (HMMA) — tcgen05 unavailable (compute_103 PTX).
// gates[B,512] = [x|h] @ Wcat^T, fp16 operands / fp32 accum, fused epilogue.
//
// R14 -> R15: fix the coherence bug. Consumer reads of g_a now use
// ld.global.cg (L2-coherent) instead of __ldg (.nc, non-coherent) — the
// acquire-flag protocol is only valid through the L2 coherence point.
// Everything else identical to R14: single fused kernel, inline W pack,
// block t converts A-tile t (then t+148) interleaved with its GEMM tiles,
// flags with release/acquire, R12 GEMM shape (148x512thr, 2mt x 8nfrag).
// ============================================================================

// A fragments: uint4 per (mt, ks, mtile, lane):
//   idx = mt*8192 + ks*512 + mtile*32 + lane   (mt: 256-row tile)
__device__ __align__(16) uint4 g_a[2097152];   // 32 MB
__device__ int g_flags[8192];                  // zero-init; tile-ready flags

__device__ __forceinline__ uint32_t smem_u32(const void* p) {
    uint32_t a;
    asm("{ .reg .u64 t; cvta.to.shared.u64 t, %1; cvt.u32.u64 %0, t; }"
        : "=r"(a) : "l"(p));
    return a;
}

__device__ __forceinline__ float fast_tanh(float x) {
    float r;
    asm("tanh.approx.f32 %0, %1;" : "=f"(r) : "f"(x));
    return r;
}
__device__ __forceinline__ float fast_sigmoid(float x) {
    return fmaf(0.5f, fast_tanh(0.5f * x), 0.5f);
}

__device__ __forceinline__ uint32_t cvt_h2(float lo, float hi) {
    uint32_t r;
    asm("cvt.rn.f16x2.f32 %0, %1, %2;" : "=r"(r) : "f"(hi), "f"(lo));
    return r;
}

__device__ __forceinline__ void mma16816(float* d, const uint32_t* a,
                                         uint32_t b0, uint32_t b1) {
    asm volatile(
        "mma.sync.aligned.m16n8k16.row.col.f32.f16.f16.f32 "
        "{%0,%1,%2,%3}, {%4,%5,%6,%7}, {%8,%9}, {%0,%1,%2,%3};\n"
        : "+f"(d[0]), "+f"(d[1]), "+f"(d[2]), "+f"(d[3])
        : "r"(a[0]), "r"(a[1]), "r"(a[2]), "r"(a[3]), "r"(b0), "r"(b1));
}

__device__ __forceinline__ void lds128(uint32_t* r, uint32_t addr) {
    asm volatile("ld.shared.v4.b32 {%0,%1,%2,%3}, [%4];\n"
                 : "=r"(r[0]), "=r"(r[1]), "=r"(r[2]), "=r"(r[3]) : "r"(addr));
}

// L2-coherent 16B load (the fix: NOT .nc — must observe cross-SM writes)
__device__ __forceinline__ uint4 ldg_cg_u4(const void* p) {
    uint4 v;
    asm volatile("ld.global.cg.v4.b32 {%0,%1,%2,%3}, [%4];\n"
                 : "=r"(v.x), "=r"(v.y), "=r"(v.z), "=r"(v.w) : "l"(p));
    return v;
}

__device__ __forceinline__ float2 ldg_cs_f2(const float* p) {
    float2 v;
    asm volatile("ld.global.cs.v2.f32 {%0,%1}, [%2];\n"
                 : "=f"(v.x), "=f"(v.y) : "l"(p));
    return v;
}
__device__ __forceinline__ void stg_cs_f2(float* p, float a, float b) {
    asm volatile("st.global.cs.v2.f32 [%0], {%1,%2};\n"
                 :: "l"(p), "f"(a), "f"(b));
}

__device__ __forceinline__ void flag_set(int t) {
    asm volatile("st.release.gpu.b32 [%0], %1;\n"
                 :: "l"(&g_flags[t]), "r"(1) : "memory");
}
__device__ __forceinline__ void flag_wait(int t) {
    const int* f = &g_flags[t];
    uint32_t v;
    while (true) {
        asm volatile("ld.acquire.gpu.b32 %0, [%1];\n"
                     : "=r"(v) : "l"(f) : "memory");
        if (v) break;
        __nanosleep(200);
    }
}

// ---------------- SMEM layout (dynamic) ----------------
static constexpr int SMEM_W  = 0;
static constexpr int SMEM_BS = 65536;
static constexpr int SMEM_TOTAL = SMEM_BS + 512;

// ============================================================================
// Fused kernel. grid=148 x 512 threads, 1 CTA/SM.
// blk&3 = qh (hcol quarter); blk>>2 (0..36) strides batch tiles of 256 rows.
// Warp w (16): mgroup = w&7 (mtiles 2mg, 2mg+1), g = w>>3 (ntp half).
// Block blk also converts A-tiles blk, blk+148, ... (flag-published).
// ============================================================================
__global__ void __launch_bounds__(512, 1)
lstm_fused_kernel(
    const float* __restrict__ x, const float* __restrict__ h_t,
    const float* __restrict__ c_t,
    const float* __restrict__ Wii, const float* __restrict__ Whi,
    const float* __restrict__ Wif, const float* __restrict__ Whf,
    const float* __restrict__ Wig, const float* __restrict__ Whg,
    const float* __restrict__ Wio, const float* __restrict__ Who,
    const float* __restrict__ b_i, const float* __restrict__ b_f,
    const float* __restrict__ b_g, const float* __restrict__ b_o,
    float* __restrict__ out, int batch, int ntiles)
{
    extern __shared__ char smem[];
    const uint32_t sb = smem_u32(smem);
    const uint32_t sW = sb + SMEM_W;
    float* bs = (float*)(smem + SMEM_BS);

    const int tid  = threadIdx.x;
    const int wid  = tid >> 5;
    const int lane = tid & 31;
    const int blk  = blockIdx.x;
    const int qh   = blk & 3;
    const int cta  = blk >> 2;                 // 0..36
    const int mt_stride  = gridDim.x >> 2;     // 37
    const int cnv_stride = gridDim.x;          // 148

    // ---- inline W pack: fp32 gmem -> fp16 fragment layout in smem ----
    {
        #pragma unroll
        for (int i = 0; i < 32; i++) {
            const int p  = tid + (i << 9);     // 0..16383 pair index
            const int gl = p >> 7;             // 0..127 : q*32 + hc
            const int kp = p & 127;
            const int q  = gl >> 5;
            const int hc = gl & 31;
            const int k  = kp * 2;

            const int t2   = hc >> 3;
            const int ntp  = q * 2 + (t2 >> 1);
            const int e    = t2 & 1;
            const int l    = (k >> 2) & 3;
            const int j    = (k >> 1) & 1;
            const int ln2  = (hc & 7) * 4 + l;
            const int ks   = k >> 4;

            const float* Wx;
            const float* Wh;
            switch (q) {
                case 0:  Wx = Wii; Wh = Whi; break;
                case 1:  Wx = Wif; Wh = Whf; break;
                case 2:  Wx = Wig; Wh = Whg; break;
                default: Wx = Wio; Wh = Who; break;
            }
            const int hcolg = qh * 32 + hc;
            float2 v;
            if (k < 128) v = ((const float2*)(Wx + hcolg * 128))[kp];
            else         v = ((const float2*)(Wh + hcolg * 128))[kp - 64];

            __half2 hv = __floats2half2_rn(v.x, v.y);
            const uint32_t addr = sW + (uint32_t)(ks * 4096 + ntp * 512
                                                  + ln2 * 16 + e * 8 + j * 4);
            asm volatile("st.shared.b32 [%0], %1;\n"
                         :: "r"(addr), "r"(*(uint32_t*)&hv));
        }
    }
    // ---- biases for this quarter: bs[q][hc] ----
    if (tid < 128) {
        int q  = tid >> 5;
        int hc = tid & 31;
        const float* bp = (q == 0) ? b_i : (q == 1) ? b_f : (q == 2) ? b_g : b_o;
        bs[tid] = bp[qh * 32 + hc];
    }
    __syncthreads();

    // ---- A-tile conversion lambda: tile t -> g_a fragments + flag ----
    auto conv_tile = [&](int t) {
        #pragma unroll
        for (int i = 0; i < 16; i++) {
            const int idx   = tid + (i << 9);  // 0..8191
            const int ln3   = idx & 31;
            const int mtile = (idx >> 5) & 15;
            const int ks    = (idx >> 9) & 15;

            const int r = t * 256 + mtile * 16 + (ln3 >> 2);
            const int k = ks * 16 + (ln3 & 3) * 4;
            const float* bsrc = (k < 128) ? x : h_t;
            const int kk = k & 127;

            const float4 v = __ldg((const float4*)(bsrc + (size_t)r * 128 + kk));
            const float4 u = __ldg((const float4*)(bsrc + (size_t)(r + 8) * 128 + kk));

            uint4 w;
            w.x = cvt_h2(v.x, v.y);
            w.y = cvt_h2(u.x, u.y);
            w.z = cvt_h2(v.z, v.w);
            w.w = cvt_h2(u.z, u.w);
            g_a[(size_t)t * 8192 + idx] = w;
        }
        __threadfence();
        __syncthreads();
        if (tid == 0) flag_set(t);
    };

    // ---- consumer geometry ----
    const int mgroup = wid & 7;
    const int g      = wid >> 3;
    const uint32_t bLane = sW + (uint32_t)(g * 512 + lane * 16);
    const uint32_t aOff  = (uint32_t)(mgroup * 1024 + lane * 16);  // mtile=2mg
    const size_t cbase = (size_t)batch * 128;

    // ---- first conversion before any GEMM (pipeline fill) ----
    int next_conv = blk;
    if (next_conv < ntiles) { conv_tile(next_conv); next_conv += cnv_stride; }

    // ---- pipelined tile loop: GEMM own tiles, interleave conversions ----
    for (int mt = cta; mt < ntiles; mt += mt_stride) {
        flag_wait(mt);

        float acc[2][4][2][4];                 // [mtile][gate][e][frag]
        #pragma unroll
        for (int a0 = 0; a0 < 2; a0++)
            #pragma unroll
            for (int a1 = 0; a1 < 4; a1++)
                #pragma unroll
                for (int a2 = 0; a2 < 2; a2++)
                    #pragma unroll
                    for (int a3 = 0; a3 < 4; a3++)
                        acc[a0][a1][a2][a3] = 0.0f;

        const char* aBase = (const char*)g_a + (size_t)mt * 131072 + aOff;

        uint4 Ac[2], An[2];
        Ac[0] = ldg_cg_u4(aBase);
        Ac[1] = ldg_cg_u4(aBase + 512);

        #pragma unroll
        for (int ks = 0; ks < 16; ks++) {
            if (ks < 15) {
                const char* ap = aBase + (ks + 1) * 8192;
                An[0] = ldg_cg_u4(ap);
                An[1] = ldg_cg_u4(ap + 512);
            }

            uint32_t B[4][4];
            const uint32_t bb = bLane + (uint32_t)(ks * 4096);
            #pragma unroll
            for (int q = 0; q < 4; q++)
                lds128(B[q], bb + (uint32_t)(q * 1024));

            #pragma unroll
            for (int q = 0; q < 4; q++) {
                #pragma unroll
                for (int m = 0; m < 2; m++) {
                    mma16816(acc[m][q][0], (const uint32_t*)&Ac[m], B[q][0], B[q][1]);
                    mma16816(acc[m][q][1], (const uint32_t*)&Ac[m], B[q][2], B[q][3]);
                }
            }

            Ac[0] = An[0];
            Ac[1] = An[1];
        }

        // ---- epilogue ----
        const int hc0 = (g << 4) + ((lane & 3) << 1);
        const int hcol0 = (qh << 5) + hc0;
        float2 cv[2][2][2];                    // [m][e][rh]
        #pragma unroll
        for (int m = 0; m < 2; m++) {
            const int rr0 = mt * 256 + (mgroup * 2 + m) * 16 + (lane >> 2);
            #pragma unroll
            for (int e = 0; e < 2; e++) {
                const int hcol = hcol0 + e * 8;
                cv[m][e][0] = ldg_cs_f2(c_t + (size_t)rr0 * 128 + hcol);
                cv[m][e][1] = ldg_cs_f2(c_t + (size_t)(rr0 + 8) * 128 + hcol);
            }
        }

        #pragma unroll
        for (int m = 0; m < 2; m++) {
            const int rr0 = mt * 256 + (mgroup * 2 + m) * 16 + (lane >> 2);
            #pragma unroll
            for (int e = 0; e < 2; e++) {
                const int hc32 = hc0 + e * 8;
                const int hcol = hcol0 + e * 8;
                const float bi0 = bs[hc32],      bi1 = bs[hc32 + 1];
                const float bf0 = bs[32 + hc32], bf1 = bs[32 + hc32 + 1];
                const float bg0 = bs[64 + hc32], bg1 = bs[64 + hc32 + 1];
                const float bo0 = bs[96 + hc32], bo1 = bs[96 + hc32 + 1];
                #pragma unroll
                for (int rh = 0; rh < 2; rh++) {
                    const int row = rr0 + rh * 8;
                    const float2 cc = cv[m][e][rh];

                    float ia0 = acc[m][0][e][rh * 2 + 0] + bi0;
                    float ia1 = acc[m][0][e][rh * 2 + 1] + bi1;
                    float fa0 = acc[m][1][e][rh * 2 + 0] + bf0;
                    float fa1 = acc[m][1][e][rh * 2 + 1] + bf1;
                    float ga0 = acc[m][2][e][rh * 2 + 0] + bg0;
                    float ga1 = acc[m][2][e][rh * 2 + 1] + bg1;
                    float oa0 = acc[m][3][e][rh * 2 + 0] + bo0;
                    float oa1 = acc[m][3][e][rh * 2 + 1] + bo1;

                    float it0 = fast_sigmoid(ia0), it1 = fast_sigmoid(ia1);
                    float ft0 = fast_sigmoid(fa0), ft1 = fast_sigmoid(fa1);
                    float gt0 = fast_tanh(ga0),    gt1 = fast_tanh(ga1);
                    float ot0 = fast_sigmoid(oa0), ot1 = fast_sigmoid(oa1);

                    float cn0 = ft0 * cc.x + it0 * gt0;
                    float cn1 = ft1 * cc.y + it1 * gt1;
                    float hn0 = ot0 * fast_tanh(cn0);
                    float hn1 = ot1 * fast_tanh(cn1);

                    stg_cs_f2(out + (size_t)row * 128 + hcol, hn0, hn1);
                    stg_cs_f2(out + cbase + (size_t)row * 128 + hcol, cn0, cn1);
                }
            }
        }

        // interleave next owned conversion behind this GEMM tile
        if (next_conv < ntiles) { conv_tile(next_conv); next_conv += cnv_stride; }
    }
}

// ============================================================================
// Host launch — single kernel
// ============================================================================
extern "C" void kernel_launch(void* const* d_in, const int* in_sizes, int n_in,
                              void* d_out, int out_size)
{
    (void)n_in; (void)out_size;
    const float* x   = (const float*)d_in[0];
    const float* h_t = (const float*)d_in[1];
    const float* c_t = (const float*)d_in[2];
    const float* Wii = (const float*)d_in[3];
    const float* Whi = (const float*)d_in[4];
    const float* b_i = (const float*)d_in[5];
    const float* Wif = (const float*)d_in[6];
    const float* Whf = (const float*)d_in[7];
    const float* b_f = (const float*)d_in[8];
    const float* Wig = (const float*)d_in[9];
    const float* Whg = (const float*)d_in[10];
    const float* b_g = (const float*)d_in[11];
    const float* Wio = (const float*)d_in[12];
    const float* Who = (const float*)d_in[13];
    const float* b_o = (const float*)d_in[14];

    const int batch  = in_sizes[0] / 128;
    const int ntiles = batch / 256;            // 256 for batch 65536

    static bool attr_set = false;
    if (!attr_set) {
        cudaFuncSetAttribute(lstm_fused_kernel,
                             cudaFuncAttributeMaxDynamicSharedMemorySize,
                             SMEM_TOTAL);
        attr_set = true;
    }
    lstm_fused_kernel<<<148, 512, SMEM_TOTAL>>>(
        x, h_t, c_t, Wii, Whi, Wif, Whf, Wig, Whg, Wio, Who,
        b_i, b_f, b_g, b_o, (float*)d_out, batch, ntiles);
}